// round 9
// baseline (speedup 1.0000x reference)
#include <cuda_runtime.h>
#include <math.h>

#define LSEQ 4096      // L = 16*16*16
#define NSq  8         // 4 parts * B=2 sequences
#define DI   128       // d_inner
#define DST  16        // d_state
#define NCHK 128       // scan chunks
#define CLEN 32        // chunk length
#define NCHAN (NSq*DI*DST)   // 16384 channels

typedef unsigned long long u64;

// ---------------- static device scratch ----------------
// tiled layout: [s][chunk][d][32] for dt, u(post-conv), z, y
__device__ __align__(16) float g_parts[NSq*LSEQ*64];   // [s][l][64]
__device__ __align__(16) float g_uraw [NSq*LSEQ*DI];   // [s][l][128] pre-conv u; later tiled gated-y
__device__ __align__(16) float g_zbuf [NSq*LSEQ*DI];   // tiled
__device__ __align__(16) float g_ubuf [NSq*LSEQ*DI];   // tiled
__device__ __align__(16) float g_dt   [NSq*LSEQ*DI];   // tiled
__device__ __align__(16) float g_Bm   [NSq*LSEQ*DST];  // [s][l][16]
__device__ __align__(16) float g_Cm   [NSq*LSEQ*DST];
__device__ float g_Ap[NCHK*NCHAN];
__device__ float g_Bp[NCHK*NCHAN];
__device__ float g_Hc[NCHK*NCHAN];
__device__ __align__(16) float g_xm[2*LSEQ*256];       // [b][l][256]
__device__ int g_fast;

// ---------------- f32x2 helpers ----------------
__device__ __forceinline__ u64 packdup(float w) {
    u64 r; unsigned int wi = __float_as_uint(w);
    asm("mov.b64 %0, {%1, %1};" : "=l"(r) : "r"(wi));
    return r;
}
__device__ __forceinline__ u64 fma2(u64 a, u64 b, u64 c) {
    u64 d; asm("fma.rn.f32x2 %0, %1, %2, %3;" : "=l"(d) : "l"(a), "l"(b), "l"(c));
    return d;
}
__device__ __forceinline__ float2 unpk(u64 v) {
    float2 f; asm("mov.b64 {%0, %1}, %2;" : "=f"(f.x), "=f"(f.y) : "l"(v));
    return f;
}

// ---------------- K0: detect A[d][k] == -(k+1) ----------------
__global__ void k0_check(const float* __restrict__ A_log) {
    __shared__ int ok;
    if (threadIdx.x == 0) ok = 1;
    __syncthreads();
    for (int i = threadIdx.x; i < DI*DST; i += blockDim.x) {
        int k = i & 15;
        float a = __expf(A_log[i]);
        if (fabsf(a - (float)(k + 1)) > 1e-3f * (float)(k + 1)) atomicAnd(&ok, 0);
    }
    __syncthreads();
    if (threadIdx.x == 0) g_fast = ok;
}

// ---------------- K1: LayerNorm + parts + in_proj (f32x2) ----------------
// grid (128, B, 2 p-pairs), 256 threads, ~71KB smem -> 3 blocks/SM
__global__ void __launch_bounds__(256)
k1_ln_inproj(const float* __restrict__ x, const float* __restrict__ lng,
             const float* __restrict__ lnb, const float* __restrict__ W) {
    extern __shared__ float sm[];
    float* xs  = sm;              // 256 x 34 (transposed: [c][l])
    float* ws  = xs + 256*34;     // 64 x 132  W^T e-chunk [d][e_local]
    float* gs  = ws + 64*132;     // 256
    float* bs  = gs + 256;        // 256
    float* mus = bs + 256;        // 32
    float* rss = mus + 32;        // 32

    const int tid = threadIdx.x;
    const int b   = blockIdx.y;
    const int z   = blockIdx.z;       // p-pair {2z, 2z+1}
    const int c32 = blockIdx.x;
    const int l0  = c32 * 32;

    gs[tid] = lng[tid]; bs[tid] = lnb[tid];
    #pragma unroll 4
    for (int i = 0; i < 32; i++) {    // x -> xs[c][l] (coalesced over l)
        int idx = i*256 + tid;
        int cc = idx >> 5, ll = idx & 31;
        xs[cc*34 + ll] = x[(b*256 + cc)*LSEQ + l0 + ll];
    }
    __syncthreads();

    // LN stats: warp w handles l = w*4+i
    const int w = tid >> 5, lane = tid & 31;
    for (int i = 0; i < 4; i++) {
        int ll = w*4 + i;
        float s = 0.f, s2 = 0.f;
        #pragma unroll
        for (int j = 0; j < 8; j++) {
            float v = xs[(lane + j*32)*34 + ll];
            s += v; s2 += v*v;
        }
        #pragma unroll
        for (int o = 16; o > 0; o >>= 1) {
            s  += __shfl_xor_sync(0xffffffffu, s,  o);
            s2 += __shfl_xor_sync(0xffffffffu, s2, o);
        }
        if (lane == 0) {
            float mu = s * (1.f/256.f);
            mus[ll] = mu;
            rss[ll] = rsqrtf(s2 * (1.f/256.f) - mu*mu + 1e-5f);
        }
    }
    __syncthreads();

    {   // normalize; write parts for this block's c-range
        const int c = tid;
        const float g = gs[c], bb = bs[c];
        const bool wp = (c >> 7) == z;
        const int p = c >> 6, cq = c & 63;
        #pragma unroll 4
        for (int ll = 0; ll < 32; ll++) {
            float v = (xs[c*34 + ll] - mus[ll]) * rss[ll] * g + bb;
            xs[c*34 + ll] = v;
            if (wp) g_parts[((p*2 + b)*LSEQ + l0 + ll)*64 + cq] = v;
        }
    }

    const int te = tid >> 3;          // 32: e quad
    const int tl = tid & 7;           // 8: l quad
    const int lb = tl*4;

    for (int ec = 0; ec < 2; ec++) {
        __syncthreads();
        #pragma unroll 4
        for (int i = 0; i < 32; i++) {    // W^T chunk -> ws[d][el]
            int idx = i*256 + tid;
            int d = idx & 63, el = idx >> 6;
            ws[d*132 + el] = W[(ec*128 + el)*64 + d];
        }
        __syncthreads();

        for (int pg = 0; pg < 2; pg++) {
            const int p = z*2 + pg;
            const int s = p*2 + b;
            u64 acc[4][2];
            #pragma unroll
            for (int i4 = 0; i4 < 4; i4++) { acc[i4][0] = 0ull; acc[i4][1] = 0ull; }

            #pragma unroll 2
            for (int d = 0; d < 64; d++) {
                float4 wq = *(const float4*)&ws[d*132 + te*4];
                const float* xp = xs + (p*64 + d)*34 + lb;
                u64 xa = *(const u64*)xp;
                u64 xb = *(const u64*)(xp + 2);
                u64 w0 = packdup(wq.x), w1 = packdup(wq.y);
                u64 w2 = packdup(wq.z), w3 = packdup(wq.w);
                acc[0][0] = fma2(w0, xa, acc[0][0]); acc[0][1] = fma2(w0, xb, acc[0][1]);
                acc[1][0] = fma2(w1, xa, acc[1][0]); acc[1][1] = fma2(w1, xb, acc[1][1]);
                acc[2][0] = fma2(w2, xa, acc[2][0]); acc[2][1] = fma2(w2, xb, acc[2][1]);
                acc[3][0] = fma2(w3, xa, acc[3][0]); acc[3][1] = fma2(w3, xb, acc[3][1]);
            }

            float2 pa[4], pb2[4];
            #pragma unroll
            for (int i4 = 0; i4 < 4; i4++) { pa[i4] = unpk(acc[i4][0]); pb2[i4] = unpk(acc[i4][1]); }

            if (ec == 0) {            // u-half: [s][l][128] rows, float4 over e
                float* base = g_uraw + ((size_t)s*LSEQ + l0 + lb)*128 + te*4;
                *(float4*)(base      ) = make_float4(pa[0].x,  pa[1].x,  pa[2].x,  pa[3].x);
                *(float4*)(base + 128) = make_float4(pa[0].y,  pa[1].y,  pa[2].y,  pa[3].y);
                *(float4*)(base + 256) = make_float4(pb2[0].x, pb2[1].x, pb2[2].x, pb2[3].x);
                *(float4*)(base + 384) = make_float4(pb2[0].y, pb2[1].y, pb2[2].y, pb2[3].y);
            } else {                  // z-half: tiled [s][c32][d][32], float4 over l
                float* zb = g_zbuf + (((size_t)s*NCHK + c32)*128 + te*4)*32 + lb;
                #pragma unroll
                for (int i4 = 0; i4 < 4; i4++)
                    *(float4*)(zb + i4*32) = make_float4(pa[i4].x, pa[i4].y, pb2[i4].x, pb2[i4].y);
            }
        }
    }
}

// ---------------- K2: conv + silu + x_proj + dt_proj + softplus ----------------
// grid (128, NSq), 256 threads, ~65KB -> 3 blocks/SM. dt/u stored TILED.
__global__ void __launch_bounds__(256)
k2_conv(const float* __restrict__ cw, const float* __restrict__ cb,
        const float* __restrict__ xw, const float* __restrict__ dtw,
        const float* __restrict__ dtb) {
    extern __shared__ float sm[];
    float* ur   = sm;              // 35 x 130 (halo); reused as dtt[128][33]
    float* us   = ur + 35*130;     // 32 x 130
    float* xws  = us + 32*130;     // 36 x 130
    float* dbc  = xws + 36*130;    // 32 x 40
    float* cws  = dbc + 32*40;     // 128 x 5
    float* dtws = cws + 128*5;     // 128 x 5
    float* cbs  = dtws + 128*5;    // 128
    float* dtbs = cbs + 128;       // 128

    const int tid = threadIdx.x;
    const int s   = blockIdx.y;
    const int c   = blockIdx.x;
    const int l0  = c * 32;

    for (int i = tid; i < 128*4; i += 256) {
        int ch = i >> 2, j = i & 3;
        cws[ch*5 + j]  = cw[i];
        dtws[ch*5 + j] = dtw[i];
    }
    if (tid < 128) { cbs[tid] = cb[tid]; dtbs[tid] = dtb[tid]; }
    for (int i = tid; i < 36*128; i += 256) {
        int e = i >> 7, ch = i & 127;
        xws[e*130 + ch] = xw[i];
    }
    for (int i = tid; i < 35*128; i += 256) {
        int r = i >> 7, ch = i & 127;
        int l = l0 - 3 + r;
        ur[r*130 + ch] = (l >= 0) ? g_uraw[((size_t)s*LSEQ + l)*128 + ch] : 0.f;
    }
    __syncthreads();

    for (int i = tid; i < 32*128; i += 256) {     // conv + silu -> us
        int ll = i >> 7, ch = i & 127;
        float a = cbs[ch];
        #pragma unroll
        for (int j = 0; j < 4; j++) a += cws[ch*5 + j] * ur[(ll + j)*130 + ch];
        us[ll*130 + ch] = a / (1.f + __expf(-a));
    }
    __syncthreads();

    for (int i = tid; i < 32*36; i += 256) {      // x_proj
        int ll = i / 36, e = i % 36;
        float a = 0.f;
        #pragma unroll 8
        for (int ch = 0; ch < 128; ch++) a += us[ll*130 + ch] * xws[e*130 + ch];
        dbc[ll*40 + e] = a;
    }
    __syncthreads();

    for (int i = tid; i < 32*16; i += 256) {      // write B, C
        int ll = i >> 4, k = i & 15;
        g_Bm[((size_t)s*LSEQ + l0 + ll)*16 + k] = dbc[ll*40 + 4 + k];
        g_Cm[((size_t)s*LSEQ + l0 + ll)*16 + k] = dbc[ll*40 + 20 + k];
    }
    float* dtt = ur;   // overlay: 128 x 33 (ur dead after conv)
    for (int i = tid; i < 32*128; i += 256) {     // dt_proj + softplus -> dtt[d][l]
        int ll = i >> 7, d = i & 127;
        float a = dtbs[d];
        #pragma unroll
        for (int r = 0; r < 4; r++) a += dbc[ll*40 + r] * dtws[d*5 + r];
        float sp = (a > 20.f) ? a : log1pf(__expf(a));
        dtt[d*33 + ll] = sp;
    }
    __syncthreads();

    // coalesced TILED stores: [s][c][d][32]
    const size_t tb = (((size_t)s*NCHK + c)*128)*32;
    for (int i = tid; i < 128*32; i += 256) {
        int d = i >> 5, li = i & 31;
        g_dt  [tb + i] = dtt[d*33 + li];
        g_ubuf[tb + i] = us[li*130 + d];
    }
}

// 8-power tree: q[j] = p^(j+1)
__device__ __forceinline__ void pow_tree8(float p, float* q) {
    float p2 = p*p, p4 = p2*p2;
    q[0]=p;     q[1]=p2;    q[2]=p2*p;    q[3]=p4;
    q[4]=p4*p;  q[5]=p4*p2; q[6]=p4*q[2]; q[7]=p4*p4;
}

// ---------------- K3: scan pass 1, 8 states/thread, tiled float4 loads ----------------
// grid (NCHK, NSq), 256 threads
__global__ void __launch_bounds__(256)
k3_scan1(const float* __restrict__ A_log) {
    __shared__ float Bsh[CLEN*20];
    const int tid = threadIdx.x;
    const int d   = tid & 127;
    const int kh  = tid >> 7;
    const int s   = blockIdx.y;
    const int c   = blockIdx.x;
    const int l0  = c * CLEN;

    for (int i = tid; i < CLEN*16; i += 256) {
        int l = i >> 4, k = i & 15;
        Bsh[l*20 + k] = g_Bm[((size_t)s*LSEQ + l0 + l)*16 + k];
    }
    const int fast = g_fast;
    float Areg[8];
    if (!fast) {
        #pragma unroll
        for (int k = 0; k < 8; k++) Areg[k] = -__expf(A_log[d*16 + kh*8 + k]);
    }
    __syncthreads();

    float h[8];
    #pragma unroll
    for (int k = 0; k < 8; k++) h[k] = 0.f;
    const size_t tb = (((size_t)s*NCHK + c)*128 + d)*32;
    const float4* pdt4 = (const float4*)(g_dt   + tb);
    const float4* pu4  = (const float4*)(g_ubuf + tb);
    const int ch = (s*128 + d)*16 + kh*8;

    if (fast) {
        float P = 1.f;
        #pragma unroll
        for (int i8 = 0; i8 < 8; i8++) {
            float4 dq = pdt4[i8];
            float4 uq = pu4[i8];
            float da[4] = {dq.x, dq.y, dq.z, dq.w};
            float ua[4] = {uq.x, uq.y, uq.z, uq.w};
            #pragma unroll
            for (int j = 0; j < 4; j++) {
                int l = i8*4 + j;
                float dt = da[j];
                float du = dt * ua[j];
                float p  = __expf(-dt);
                P *= p;
                float q[8]; pow_tree8(p, q);
                if (kh) {
                    float p8 = q[7];
                    #pragma unroll
                    for (int jj = 0; jj < 8; jj++) q[jj] *= p8;
                }
                float4 b0 = *(const float4*)&Bsh[l*20 + kh*8];
                float4 b1 = *(const float4*)&Bsh[l*20 + kh*8 + 4];
                h[0] = q[0]*h[0] + du*b0.x;  h[1] = q[1]*h[1] + du*b0.y;
                h[2] = q[2]*h[2] + du*b0.z;  h[3] = q[3]*h[3] + du*b0.w;
                h[4] = q[4]*h[4] + du*b1.x;  h[5] = q[5]*h[5] + du*b1.y;
                h[6] = q[6]*h[6] + du*b1.z;  h[7] = q[7]*h[7] + du*b1.w;
            }
        }
        float P2 = P*P, P4 = P2*P2, P8 = P4*P4;
        float Q = kh ? P8*P : P;
        #pragma unroll
        for (int k = 0; k < 8; k++) {
            g_Ap[c*NCHAN + ch + k] = Q;
            g_Bp[c*NCHAN + ch + k] = h[k];
            Q *= P;
        }
    } else {
        float ap[8];
        #pragma unroll
        for (int k = 0; k < 8; k++) ap[k] = 1.f;
        #pragma unroll 2
        for (int i8 = 0; i8 < 8; i8++) {
            float4 dq = pdt4[i8];
            float4 uq = pu4[i8];
            float da[4] = {dq.x, dq.y, dq.z, dq.w};
            float ua[4] = {uq.x, uq.y, uq.z, uq.w};
            #pragma unroll
            for (int j = 0; j < 4; j++) {
                int l = i8*4 + j;
                float dt = da[j];
                float du = dt * ua[j];
                const float* pB = &Bsh[l*20 + kh*8];
                #pragma unroll
                for (int k = 0; k < 8; k++) {
                    float a = __expf(dt * Areg[k]);
                    h[k]  = a*h[k] + du*pB[k];
                    ap[k] *= a;
                }
            }
        }
        #pragma unroll
        for (int k = 0; k < 8; k++) {
            g_Ap[c*NCHAN + ch + k] = ap[k];
            g_Bp[c*NCHAN + ch + k] = h[k];
        }
    }
}

// ---------------- K3b: inter-chunk carry scan ----------------
__global__ void __launch_bounds__(256)
k3b_carry() {
    int ch = blockIdx.x*256 + threadIdx.x;
    float h = 0.f;
    #pragma unroll 4
    for (int c = 0; c < NCHK; c++) {
        g_Hc[c*NCHAN + ch] = h;
        h = g_Ap[c*NCHAN + ch]*h + g_Bp[c*NCHAN + ch];
    }
}

// ---------------- K4: scan pass 2 + gate -> tiled y in g_uraw ----------------
// grid (NCHK, NSq), 256 threads. warp w: d = w*16 + (lane&15), kh = lane>>4
__global__ void __launch_bounds__(256)
k4_scan2(const float* __restrict__ A_log, const float* __restrict__ Dp) {
    __shared__ float Bsh[CLEN*20];
    __shared__ float Csh[CLEN*20];
    const int tid  = threadIdx.x;
    const int w    = tid >> 5, lane = tid & 31;
    const int d    = w*16 + (lane & 15);
    const int kh   = lane >> 4;
    const int s    = blockIdx.y;
    const int c    = blockIdx.x;
    const int l0   = c * CLEN;

    for (int i = tid; i < CLEN*16; i += 256) {
        int l = i >> 4, k = i & 15;
        Bsh[l*20 + k] = g_Bm[((size_t)s*LSEQ + l0 + l)*16 + k];
        Csh[l*20 + k] = g_Cm[((size_t)s*LSEQ + l0 + l)*16 + k];
    }
    const int fast = g_fast;
    float Areg[8];
    if (!fast) {
        #pragma unroll
        for (int k = 0; k < 8; k++) Areg[k] = -__expf(A_log[d*16 + kh*8 + k]);
    }
    float h[8];
    {
        const int ch = (s*128 + d)*16 + kh*8;
        #pragma unroll
        for (int k = 0; k < 8; k++) h[k] = g_Hc[c*NCHAN + ch + k];
    }
    const float Dd = Dp[d];
    __syncthreads();

    const size_t tb = (((size_t)s*NCHK + c)*128 + d)*32;
    const float4* pdt4 = (const float4*)(g_dt   + tb);
    const float4* pu4  = (const float4*)(g_ubuf + tb);
    const float4* pz4  = (const float4*)(g_zbuf + tb);
    float4*       py4  = (float4*)(g_uraw + tb);   // tiled gated-y

    if (fast) {
        #pragma unroll 2
        for (int i8 = 0; i8 < 8; i8++) {
            float4 dq = pdt4[i8];
            float4 uq = pu4[i8];
            float4 zq = pz4[i8];
            float da[4] = {dq.x, dq.y, dq.z, dq.w};
            float ua[4] = {uq.x, uq.y, uq.z, uq.w};
            float za[4] = {zq.x, zq.y, zq.z, zq.w};
            float yo[4];
            #pragma unroll
            for (int j = 0; j < 4; j++) {
                int l = i8*4 + j;
                float dt = da[j];
                float uu = ua[j];
                float du = dt * uu;
                float p  = __expf(-dt);
                float q[8]; pow_tree8(p, q);
                float p8m = kh ? q[7] : 1.f;
                #pragma unroll
                for (int jj = 0; jj < 8; jj++) q[jj] *= p8m;
                float4 b0 = *(const float4*)&Bsh[l*20 + kh*8];
                float4 b1 = *(const float4*)&Bsh[l*20 + kh*8 + 4];
                float4 c0 = *(const float4*)&Csh[l*20 + kh*8];
                float4 c1 = *(const float4*)&Csh[l*20 + kh*8 + 4];
                float y = kh ? 0.f : Dd * uu;
                h[0] = q[0]*h[0] + du*b0.x;  y += h[0]*c0.x;
                h[1] = q[1]*h[1] + du*b0.y;  y += h[1]*c0.y;
                h[2] = q[2]*h[2] + du*b0.z;  y += h[2]*c0.z;
                h[3] = q[3]*h[3] + du*b0.w;  y += h[3]*c0.w;
                h[4] = q[4]*h[4] + du*b1.x;  y += h[4]*c1.x;
                h[5] = q[5]*h[5] + du*b1.y;  y += h[5]*c1.y;
                h[6] = q[6]*h[6] + du*b1.z;  y += h[6]*c1.z;
                h[7] = q[7]*h[7] + du*b1.w;  y += h[7]*c1.w;
                y += __shfl_xor_sync(0xffffffffu, y, 16);
                float zv = za[j];
                float sg = 1.f / (1.f + __expf(-zv));
                yo[j] = y * zv * sg;
            }
            if (kh == 0) py4[i8] = make_float4(yo[0], yo[1], yo[2], yo[3]);
        }
    } else {
        #pragma unroll 2
        for (int i8 = 0; i8 < 8; i8++) {
            float4 dq = pdt4[i8];
            float4 uq = pu4[i8];
            float4 zq = pz4[i8];
            float da[4] = {dq.x, dq.y, dq.z, dq.w};
            float ua[4] = {uq.x, uq.y, uq.z, uq.w};
            float za[4] = {zq.x, zq.y, zq.z, zq.w};
            float yo[4];
            #pragma unroll
            for (int j = 0; j < 4; j++) {
                int l = i8*4 + j;
                float dt = da[j];
                float uu = ua[j];
                float du = dt * uu;
                const float* pB = &Bsh[l*20 + kh*8];
                const float* pC = &Csh[l*20 + kh*8];
                float y = kh ? 0.f : Dd * uu;
                #pragma unroll
                for (int k = 0; k < 8; k++) {
                    float a = __expf(dt * Areg[k]);
                    h[k] = a*h[k] + du*pB[k];
                    y   += h[k]*pC[k];
                }
                y += __shfl_xor_sync(0xffffffffu, y, 16);
                float zv = za[j];
                float sg = 1.f / (1.f + __expf(-zv));
                yo[j] = y * zv * sg;
            }
            if (kh == 0) py4[i8] = make_float4(yo[0], yo[1], yo[2], yo[3]);
        }
    }
}

// ---------------- K4b: out_proj GEMM (f32x2) + skip -> g_xm ----------------
// grid (64, NSq), 256 threads, ~69KB smem (dynamic) -> 3 blocks/SM
__global__ void __launch_bounds__(256)
k4b_outproj(const float* __restrict__ Wout, const float* __restrict__ skip) {
    extern __shared__ float sm[];
    float* ys  = sm;             // 128 x 66  y tile [d][l] (64 l + pad 2)
    float* wsh = ys + 128*66;    // 128 x 68  Wout^T [d][o]
    const int tid = threadIdx.x;
    const int s   = blockIdx.y;
    const int l0  = blockIdx.x * 64;
    const size_t ybase = (((size_t)s*NCHK + blockIdx.x*2)*128)*32;  // 2 chunks contiguous

    for (int i = tid; i < 8192; i += 256) {       // tiled y -> ys[d][l]
        int li = i & 31, d = (i >> 5) & 127, chh = i >> 12;
        ys[d*66 + chh*32 + li] = g_uraw[ybase + i];
    }
    for (int i = tid; i < 8192; i += 256) {       // Wout -> wsh[d][o]
        int d = i & 127, o = i >> 7;
        wsh[d*68 + o] = Wout[i];
    }
    __syncthreads();

    const int to = tid >> 4;          // 16: o quad, o0 = to*4 in [0,64)
    const int tl = tid & 15;          // 16: l quad, lb = tl*4 in [0,64)
    const int o0 = to*4, lb = tl*4;
    u64 acc[4][2];
    #pragma unroll
    for (int i4 = 0; i4 < 4; i4++) { acc[i4][0] = 0ull; acc[i4][1] = 0ull; }

    #pragma unroll 2
    for (int d = 0; d < 128; d++) {
        float4 wq = *(const float4*)&wsh[d*68 + o0];
        const float* yp = ys + d*66 + lb;
        u64 xa = *(const u64*)yp;
        u64 xb = *(const u64*)(yp + 2);
        u64 w0 = packdup(wq.x), w1 = packdup(wq.y);
        u64 w2 = packdup(wq.z), w3 = packdup(wq.w);
        acc[0][0] = fma2(w0, xa, acc[0][0]); acc[0][1] = fma2(w0, xb, acc[0][1]);
        acc[1][0] = fma2(w1, xa, acc[1][0]); acc[1][1] = fma2(w1, xb, acc[1][1]);
        acc[2][0] = fma2(w2, xa, acc[2][0]); acc[2][1] = fma2(w2, xb, acc[2][1]);
        acc[3][0] = fma2(w3, xa, acc[3][0]); acc[3][1] = fma2(w3, xb, acc[3][1]);
    }

    float yv[4][4];
    #pragma unroll
    for (int i4 = 0; i4 < 4; i4++) {
        float2 a = unpk(acc[i4][0]), bb = unpk(acc[i4][1]);
        yv[i4][0] = a.x; yv[i4][1] = a.y; yv[i4][2] = bb.x; yv[i4][3] = bb.y;
    }

    const float sk = skip[0];
    const int p = s >> 1, b = s & 1;
    #pragma unroll
    for (int j = 0; j < 4; j++) {
        int l = l0 + lb + j;
        float4 pv = *(const float4*)&g_parts[((size_t)s*LSEQ + l)*64 + o0];
        float4 ov = make_float4(yv[0][j] + sk*pv.x, yv[1][j] + sk*pv.y,
                                yv[2][j] + sk*pv.z, yv[3][j] + sk*pv.w);
        *(float4*)&g_xm[((size_t)b*LSEQ + l)*256 + p*64 + o0] = ov;
    }
}

// ---------------- K5: final LN + 256x256 proj (f32x2) + bias + transpose ----------------
// grid (128, B, 2 o-halves), 256 threads, ~71KB -> 3 blocks/SM
__global__ void __launch_bounds__(256)
k5_ln_proj(const float* __restrict__ lng, const float* __restrict__ lnb,
           const float* __restrict__ Wp, const float* __restrict__ bp,
           float* __restrict__ out) {
    extern __shared__ float sm[];
    float* xs  = sm;              // 256 x 34 (transposed [c][l])
    float* wt  = xs + 256*34;     // 64 x 132  Wp^T c-chunk [c'][o_local]
    float* gs  = wt + 64*132;     // 256
    float* bs  = gs + 256;        // 256
    float* mus = bs + 256;        // 32
    float* rss = mus + 32;        // 32

    const int tid = threadIdx.x;
    const int b   = blockIdx.y;
    const int z   = blockIdx.z;       // o-half
    const int l0  = blockIdx.x * 32;

    gs[tid] = lng[tid]; bs[tid] = lnb[tid];
    #pragma unroll 4
    for (int i = 0; i < 32; i++)      // g_xm[b][l][c] -> xs[c][l] (coalesced over c)
        xs[tid*34 + i] = g_xm[((size_t)b*LSEQ + l0 + i)*256 + tid];
    __syncthreads();

    const int w = tid >> 5, lane = tid & 31;
    for (int i = 0; i < 4; i++) {
        int ll = w*4 + i;
        float s = 0.f, s2 = 0.f;
        #pragma unroll
        for (int j = 0; j < 8; j++) {
            float v = xs[(lane + j*32)*34 + ll];
            s += v; s2 += v*v;
        }
        #pragma unroll
        for (int o = 16; o > 0; o >>= 1) {
            s  += __shfl_xor_sync(0xffffffffu, s,  o);
            s2 += __shfl_xor_sync(0xffffffffu, s2, o);
        }
        if (lane == 0) {
            float mu = s * (1.f/256.f);
            mus[ll] = mu;
            rss[ll] = rsqrtf(s2 * (1.f/256.f) - mu*mu + 1e-5f);
        }
    }
    __syncthreads();
    {
        const int c = tid;
        const float g = gs[c], bb = bs[c];
        #pragma unroll 4
        for (int ll = 0; ll < 32; ll++)
            xs[c*34 + ll] = (xs[c*34 + ll] - mus[ll]) * rss[ll] * g + bb;
    }

    const int to = tid >> 3;          // 32: o quad, ol0 = to*4 in [0,128)
    const int tl = tid & 7;           // 8: l quad, lb = tl*4
    const int ol0 = to*4, lb = tl*4;
    float4 pbv = *(const float4*)&bp[z*128 + ol0];
    u64 acc[4][2];
    acc[0][0] = packdup(pbv.x); acc[0][1] = acc[0][0];
    acc[1][0] = packdup(pbv.y); acc[1][1] = acc[1][0];
    acc[2][0] = packdup(pbv.z); acc[2][1] = acc[2][0];
    acc[3][0] = packdup(pbv.w); acc[3][1] = acc[3][0];

    for (int cchunk = 0; cchunk < 4; cchunk++) {
        const int c0 = cchunk*64;
        __syncthreads();
        #pragma unroll 4
        for (int i = 0; i < 32; i++) {         // Wp chunk -> wt[c'][o_local]
            int idx = i*256 + tid;
            int cc = idx & 63, ol = idx >> 6;
            wt[cc*132 + ol] = Wp[(z*128 + ol)*256 + c0 + cc];
        }
        __syncthreads();
        #pragma unroll 2
        for (int cc = 0; cc < 64; cc++) {
            float4 wq = *(const float4*)&wt[cc*132 + ol0];
            const float* xp = xs + (c0 + cc)*34 + lb;
            u64 xa = *(const u64*)xp;
            u64 xb = *(const u64*)(xp + 2);
            u64 w0 = packdup(wq.x), w1 = packdup(wq.y);
            u64 w2 = packdup(wq.z), w3 = packdup(wq.w);
            acc[0][0] = fma2(w0, xa, acc[0][0]); acc[0][1] = fma2(w0, xb, acc[0][1]);
            acc[1][0] = fma2(w1, xa, acc[1][0]); acc[1][1] = fma2(w1, xb, acc[1][1]);
            acc[2][0] = fma2(w2, xa, acc[2][0]); acc[2][1] = fma2(w2, xb, acc[2][1]);
            acc[3][0] = fma2(w3, xa, acc[3][0]); acc[3][1] = fma2(w3, xb, acc[3][1]);
        }
    }

    // direct stores: per o, float4 over l (out is [b][o][L])
    #pragma unroll
    for (int i4 = 0; i4 < 4; i4++) {
        float2 a = unpk(acc[i4][0]), bb = unpk(acc[i4][1]);
        *(float4*)&out[((size_t)b*256 + z*128 + ol0 + i4)*LSEQ + l0 + lb] =
            make_float4(a.x, a.y, bb.x, bb.y);
    }
}

// ---------------- launch ----------------
extern "C" void kernel_launch(void* const* d_in, const int* in_sizes, int n_in,
                              void* d_out, int out_size) {
    const float* x     = (const float*)d_in[0];
    const float* ln_g  = (const float*)d_in[1];
    const float* ln_b  = (const float*)d_in[2];
    const float* skip  = (const float*)d_in[3];
    const float* inw   = (const float*)d_in[4];
    const float* convw = (const float*)d_in[5];
    const float* convb = (const float*)d_in[6];
    const float* xprojw= (const float*)d_in[7];
    const float* dtw   = (const float*)d_in[8];
    const float* dtb   = (const float*)d_in[9];
    const float* A_log = (const float*)d_in[10];
    const float* Dp    = (const float*)d_in[11];
    const float* outw  = (const float*)d_in[12];
    const float* projw = (const float*)d_in[13];
    const float* projb = (const float*)d_in[14];
    float* out = (float*)d_out;

    const int SM1  = (256*34 + 64*132 + 256+256+32+32) * 4;
    const int SM2  = (35*130 + 32*130 + 36*130 + 32*40 + 128*5 + 128*5 + 128 + 128) * 4;
    const int SM4B = (128*66 + 128*68) * 4;
    const int SM5  = SM1;

    cudaFuncSetAttribute(k1_ln_inproj, cudaFuncAttributeMaxDynamicSharedMemorySize, SM1);
    cudaFuncSetAttribute(k2_conv,      cudaFuncAttributeMaxDynamicSharedMemorySize, SM2);
    cudaFuncSetAttribute(k4b_outproj,  cudaFuncAttributeMaxDynamicSharedMemorySize, SM4B);
    cudaFuncSetAttribute(k5_ln_proj,   cudaFuncAttributeMaxDynamicSharedMemorySize, SM5);

    k0_check<<<1, 256>>>(A_log);
    k1_ln_inproj<<<dim3(128, 2, 2), 256, SM1>>>(x, ln_g, ln_b, inw);
    k2_conv<<<dim3(128, NSq), 256, SM2>>>(convw, convb, xprojw, dtw, dtb);
    k3_scan1<<<dim3(NCHK, NSq), 256>>>(A_log);
    k3b_carry<<<NCHAN/256, 256>>>();
    k4_scan2<<<dim3(NCHK, NSq), 256>>>(A_log, Dp);
    k4b_outproj<<<dim3(64, NSq), 256, SM4B>>>(outw, skip);
    k5_ln_proj<<<dim3(128, 2, 2), 256, SM5>>>(ln_g, ln_b, projw, projb, out);
}

// round 13
// speedup vs baseline: 1.4421x; 1.4421x over previous
#include <cuda_runtime.h>
#include <math.h>

#define LSEQ 4096      // L = 16*16*16
#define NSq  8         // 4 parts * B=2 sequences
#define DI   128       // d_inner
#define DST  16        // d_state
#define NCHK 128       // scan chunks
#define CLEN 32        // chunk length
#define NCHAN (NSq*DI*DST)   // 16384 channels

typedef unsigned long long u64;

// ---------------- static device scratch (ALL row layout [s][l][dim]) ----------------
__device__ __align__(16) float g_parts[NSq*LSEQ*64];   // [s][l][64]
__device__ __align__(16) float g_uraw [NSq*LSEQ*DI];   // pre-conv u; later gated-y rows
__device__ __align__(16) float g_zbuf [NSq*LSEQ*DI];
__device__ __align__(16) float g_ubuf [NSq*LSEQ*DI];
__device__ __align__(16) float g_dt   [NSq*LSEQ*DI];
__device__ __align__(16) float g_Bm   [NSq*LSEQ*DST];
__device__ __align__(16) float g_Cm   [NSq*LSEQ*DST];
__device__ float g_Ap[NCHK*NCHAN];
__device__ float g_Bp[NCHK*NCHAN];
__device__ float g_Hc[NCHK*NCHAN];
__device__ __align__(16) float g_xm[2*LSEQ*256];       // [b][l][256]
__device__ int g_fast;

// ---------------- f32x2 helpers ----------------
__device__ __forceinline__ u64 packdup(float w) {
    u64 r; unsigned int wi = __float_as_uint(w);
    asm("mov.b64 %0, {%1, %1};" : "=l"(r) : "r"(wi));
    return r;
}
__device__ __forceinline__ u64 fma2(u64 a, u64 b, u64 c) {
    u64 d; asm("fma.rn.f32x2 %0, %1, %2, %3;" : "=l"(d) : "l"(a), "l"(b), "l"(c));
    return d;
}
__device__ __forceinline__ float2 unpk(u64 v) {
    float2 f; asm("mov.b64 {%0, %1}, %2;" : "=f"(f.x), "=f"(f.y) : "l"(v));
    return f;
}

// ---------------- K0: detect A[d][k] == -(k+1) ----------------
__global__ void k0_check(const float* __restrict__ A_log) {
    __shared__ int ok;
    if (threadIdx.x == 0) ok = 1;
    __syncthreads();
    for (int i = threadIdx.x; i < DI*DST; i += blockDim.x) {
        int k = i & 15;
        float a = __expf(A_log[i]);
        if (fabsf(a - (float)(k + 1)) > 1e-3f * (float)(k + 1)) atomicAnd(&ok, 0);
    }
    __syncthreads();
    if (threadIdx.x == 0) g_fast = ok;
}

// ---------------- K1: LayerNorm + parts + in_proj (f32x2) ----------------
// grid (128, B, 2 p-pairs), 256 threads, ~69KB smem
__global__ void __launch_bounds__(256)
k1_ln_inproj(const float* __restrict__ x, const float* __restrict__ lng,
             const float* __restrict__ lnb, const float* __restrict__ W) {
    extern __shared__ float sm[];
    float* xs  = sm;              // 256 x 34 (transposed: [c][l])
    float* ws  = xs + 256*34;     // 64 x 132  W^T e-chunk [d][e_local]
    float* gs  = ws + 64*132;     // 256
    float* bs  = gs + 256;        // 256
    float* mus = bs + 256;        // 32
    float* rss = mus + 32;        // 32

    const int tid = threadIdx.x;
    const int b   = blockIdx.y;
    const int z   = blockIdx.z;       // p-pair {2z, 2z+1}
    const int c32 = blockIdx.x;
    const int l0  = c32 * 32;

    gs[tid] = lng[tid]; bs[tid] = lnb[tid];
    #pragma unroll 4
    for (int i = 0; i < 32; i++) {    // x -> xs[c][l] (coalesced over l)
        int idx = i*256 + tid;
        int cc = idx >> 5, ll = idx & 31;
        xs[cc*34 + ll] = x[(b*256 + cc)*LSEQ + l0 + ll];
    }
    __syncthreads();

    const int w = tid >> 5, lane = tid & 31;
    for (int i = 0; i < 4; i++) {     // LN stats
        int ll = w*4 + i;
        float s = 0.f, s2 = 0.f;
        #pragma unroll
        for (int j = 0; j < 8; j++) {
            float v = xs[(lane + j*32)*34 + ll];
            s += v; s2 += v*v;
        }
        #pragma unroll
        for (int o = 16; o > 0; o >>= 1) {
            s  += __shfl_xor_sync(0xffffffffu, s,  o);
            s2 += __shfl_xor_sync(0xffffffffu, s2, o);
        }
        if (lane == 0) {
            float mu = s * (1.f/256.f);
            mus[ll] = mu;
            rss[ll] = rsqrtf(s2 * (1.f/256.f) - mu*mu + 1e-5f);
        }
    }
    __syncthreads();

    {   // normalize; write parts once
        const int c = tid;
        const float g = gs[c], bb = bs[c];
        const bool wp = (c >> 7) == z;
        const int p = c >> 6, cq = c & 63;
        #pragma unroll 4
        for (int ll = 0; ll < 32; ll++) {
            float v = (xs[c*34 + ll] - mus[ll]) * rss[ll] * g + bb;
            xs[c*34 + ll] = v;
            if (wp) g_parts[((p*2 + b)*LSEQ + l0 + ll)*64 + cq] = v;
        }
    }

    const int te = tid >> 3;          // 32: e quad
    const int tl = tid & 7;           // 8: l quad
    const int lb = tl*4;

    for (int ec = 0; ec < 2; ec++) {
        __syncthreads();
        #pragma unroll 4
        for (int i = 0; i < 32; i++) {    // W^T chunk -> ws[d][el]
            int idx = i*256 + tid;
            int d = idx & 63, el = idx >> 6;
            ws[d*132 + el] = W[(ec*128 + el)*64 + d];
        }
        __syncthreads();

        for (int pg = 0; pg < 2; pg++) {
            const int p = z*2 + pg;
            const int s = p*2 + b;
            u64 acc[4][2];
            #pragma unroll
            for (int i4 = 0; i4 < 4; i4++) { acc[i4][0] = 0ull; acc[i4][1] = 0ull; }

            #pragma unroll 2
            for (int d = 0; d < 64; d++) {
                float4 wq = *(const float4*)&ws[d*132 + te*4];
                const float* xp = xs + (p*64 + d)*34 + lb;
                u64 xa = *(const u64*)xp;
                u64 xb = *(const u64*)(xp + 2);
                u64 w0 = packdup(wq.x), w1 = packdup(wq.y);
                u64 w2 = packdup(wq.z), w3 = packdup(wq.w);
                acc[0][0] = fma2(w0, xa, acc[0][0]); acc[0][1] = fma2(w0, xb, acc[0][1]);
                acc[1][0] = fma2(w1, xa, acc[1][0]); acc[1][1] = fma2(w1, xb, acc[1][1]);
                acc[2][0] = fma2(w2, xa, acc[2][0]); acc[2][1] = fma2(w2, xb, acc[2][1]);
                acc[3][0] = fma2(w3, xa, acc[3][0]); acc[3][1] = fma2(w3, xb, acc[3][1]);
            }

            float2 pa[4], pb2[4];
            #pragma unroll
            for (int i4 = 0; i4 < 4; i4++) { pa[i4] = unpk(acc[i4][0]); pb2[i4] = unpk(acc[i4][1]); }

            // ROW stores: [s][l][128], float4 over e (both halves)
            float* dst = (ec == 0) ? g_uraw : g_zbuf;
            float* base = dst + ((size_t)s*LSEQ + l0 + lb)*128 + te*4;
            *(float4*)(base      ) = make_float4(pa[0].x,  pa[1].x,  pa[2].x,  pa[3].x);
            *(float4*)(base + 128) = make_float4(pa[0].y,  pa[1].y,  pa[2].y,  pa[3].y);
            *(float4*)(base + 256) = make_float4(pb2[0].x, pb2[1].x, pb2[2].x, pb2[3].x);
            *(float4*)(base + 384) = make_float4(pb2[0].y, pb2[1].y, pb2[2].y, pb2[3].y);
        }
    }
}

// ---------------- K2: conv + silu + x_proj + dt_proj + softplus ----------------
// grid (128, NSq), 256 threads, ~63KB smem
__global__ void __launch_bounds__(256)
k2_conv(const float* __restrict__ cw, const float* __restrict__ cb,
        const float* __restrict__ xw, const float* __restrict__ dtw,
        const float* __restrict__ dtb) {
    extern __shared__ float sm[];
    float* ur   = sm;              // 35 x 130 (halo)
    float* us   = ur + 35*130;     // 32 x 130
    float* xws  = us + 32*130;     // 36 x 130
    float* dbc  = xws + 36*130;    // 32 x 40
    float* cws  = dbc + 32*40;     // 128 x 5
    float* dtws = cws + 128*5;     // 128 x 5
    float* cbs  = dtws + 128*5;    // 128
    float* dtbs = cbs + 128;       // 128

    const int tid = threadIdx.x;
    const int s   = blockIdx.y;
    const int l0  = blockIdx.x * 32;

    for (int i = tid; i < 128*4; i += 256) {
        int ch = i >> 2, j = i & 3;
        cws[ch*5 + j]  = cw[i];
        dtws[ch*5 + j] = dtw[i];
    }
    if (tid < 128) { cbs[tid] = cb[tid]; dtbs[tid] = dtb[tid]; }
    for (int i = tid; i < 36*128; i += 256) {
        int e = i >> 7, ch = i & 127;
        xws[e*130 + ch] = xw[i];
    }
    for (int i = tid; i < 35*128; i += 256) {
        int r = i >> 7, ch = i & 127;
        int l = l0 - 3 + r;
        ur[r*130 + ch] = (l >= 0) ? g_uraw[((size_t)s*LSEQ + l)*128 + ch] : 0.f;
    }
    __syncthreads();

    for (int i = tid; i < 32*128; i += 256) {     // conv + silu -> us + row store
        int ll = i >> 7, ch = i & 127;
        float a = cbs[ch];
        #pragma unroll
        for (int j = 0; j < 4; j++) a += cws[ch*5 + j] * ur[(ll + j)*130 + ch];
        float v = a / (1.f + __expf(-a));
        us[ll*130 + ch] = v;
        g_ubuf[((size_t)s*LSEQ + l0 + ll)*128 + ch] = v;
    }
    __syncthreads();

    for (int i = tid; i < 32*36; i += 256) {      // x_proj
        int ll = i / 36, e = i % 36;
        float a = 0.f;
        #pragma unroll 8
        for (int ch = 0; ch < 128; ch++) a += us[ll*130 + ch] * xws[e*130 + ch];
        dbc[ll*40 + e] = a;
    }
    __syncthreads();

    for (int i = tid; i < 32*16; i += 256) {      // write B, C
        int ll = i >> 4, k = i & 15;
        g_Bm[((size_t)s*LSEQ + l0 + ll)*16 + k] = dbc[ll*40 + 4 + k];
        g_Cm[((size_t)s*LSEQ + l0 + ll)*16 + k] = dbc[ll*40 + 20 + k];
    }
    for (int i = tid; i < 32*128; i += 256) {     // dt_proj + softplus, row store
        int ll = i >> 7, d = i & 127;
        float a = dtbs[d];
        #pragma unroll
        for (int r = 0; r < 4; r++) a += dbc[ll*40 + r] * dtws[d*5 + r];
        float sp = (a > 20.f) ? a : log1pf(__expf(a));
        g_dt[((size_t)s*LSEQ + l0 + ll)*128 + d] = sp;
    }
}

// 8-power tree: q[j] = p^(j+1)
__device__ __forceinline__ void pow_tree8(float p, float* q) {
    float p2 = p*p, p4 = p2*p2;
    q[0]=p;     q[1]=p2;    q[2]=p2*p;    q[3]=p4;
    q[4]=p4*p;  q[5]=p4*p2; q[6]=p4*q[2]; q[7]=p4*p4;
}

// ---------------- K3: scan pass 1, 8 states/thread, row-coalesced loads ----------------
// grid (NCHK, NSq), 256 threads: d = tid&127, kh = tid>>7
__global__ void __launch_bounds__(256)
k3_scan1(const float* __restrict__ A_log) {
    __shared__ float Bsh[CLEN*20];
    const int tid = threadIdx.x;
    const int d   = tid & 127;
    const int kh  = tid >> 7;
    const int s   = blockIdx.y;
    const int c   = blockIdx.x;
    const int l0  = c * CLEN;

    for (int i = tid; i < CLEN*16; i += 256) {
        int l = i >> 4, k = i & 15;
        Bsh[l*20 + k] = g_Bm[((size_t)s*LSEQ + l0 + l)*16 + k];
    }
    const int fast = g_fast;
    float Areg[8];
    if (!fast) {
        #pragma unroll
        for (int k = 0; k < 8; k++) Areg[k] = -__expf(A_log[d*16 + kh*8 + k]);
    }
    __syncthreads();

    float h[8];
    #pragma unroll
    for (int k = 0; k < 8; k++) h[k] = 0.f;
    const float* pdt = g_dt   + ((size_t)s*LSEQ + l0)*128 + d;
    const float* pu  = g_ubuf + ((size_t)s*LSEQ + l0)*128 + d;
    const int ch = (s*128 + d)*16 + kh*8;

    if (fast) {
        float P = 1.f;
        #pragma unroll 4
        for (int l = 0; l < CLEN; l++) {
            float dt = pdt[l*128];
            float du = dt * pu[l*128];
            float p  = __expf(-dt);
            P *= p;
            float q[8]; pow_tree8(p, q);
            if (kh) {
                float p8 = q[7];
                #pragma unroll
                for (int jj = 0; jj < 8; jj++) q[jj] *= p8;
            }
            float4 b0 = *(const float4*)&Bsh[l*20 + kh*8];
            float4 b1 = *(const float4*)&Bsh[l*20 + kh*8 + 4];
            h[0] = q[0]*h[0] + du*b0.x;  h[1] = q[1]*h[1] + du*b0.y;
            h[2] = q[2]*h[2] + du*b0.z;  h[3] = q[3]*h[3] + du*b0.w;
            h[4] = q[4]*h[4] + du*b1.x;  h[5] = q[5]*h[5] + du*b1.y;
            h[6] = q[6]*h[6] + du*b1.z;  h[7] = q[7]*h[7] + du*b1.w;
        }
        float P2 = P*P, P4 = P2*P2, P8 = P4*P4;
        float Q = kh ? P8*P : P;
        #pragma unroll
        for (int k = 0; k < 8; k++) {
            g_Ap[c*NCHAN + ch + k] = Q;
            g_Bp[c*NCHAN + ch + k] = h[k];
            Q *= P;
        }
    } else {
        float ap[8];
        #pragma unroll
        for (int k = 0; k < 8; k++) ap[k] = 1.f;
        #pragma unroll 2
        for (int l = 0; l < CLEN; l++) {
            float dt = pdt[l*128];
            float du = dt * pu[l*128];
            const float* pB = &Bsh[l*20 + kh*8];
            #pragma unroll
            for (int k = 0; k < 8; k++) {
                float a = __expf(dt * Areg[k]);
                h[k]  = a*h[k] + du*pB[k];
                ap[k] *= a;
            }
        }
        #pragma unroll
        for (int k = 0; k < 8; k++) {
            g_Ap[c*NCHAN + ch + k] = ap[k];
            g_Bp[c*NCHAN + ch + k] = h[k];
        }
    }
}

// ---------------- K3b: inter-chunk carry scan ----------------
__global__ void __launch_bounds__(256)
k3b_carry() {
    int ch = blockIdx.x*256 + threadIdx.x;
    float h = 0.f;
    #pragma unroll 4
    for (int c = 0; c < NCHK; c++) {
        g_Hc[c*NCHAN + ch] = h;
        h = g_Ap[c*NCHAN + ch]*h + g_Bp[c*NCHAN + ch];
    }
}

// ---------------- K4: scan pass 2 + gate -> y rows in g_uraw ----------------
// grid (NCHK, NSq), 256 threads. warp w: d = w*16 + (lane&15), kh = lane>>4
__global__ void __launch_bounds__(256)
k4_scan2(const float* __restrict__ A_log, const float* __restrict__ Dp) {
    __shared__ float Bsh[CLEN*20];
    __shared__ float Csh[CLEN*20];
    const int tid  = threadIdx.x;
    const int w    = tid >> 5, lane = tid & 31;
    const int d    = w*16 + (lane & 15);
    const int kh   = lane >> 4;
    const int s    = blockIdx.y;
    const int c    = blockIdx.x;
    const int l0   = c * CLEN;

    for (int i = tid; i < CLEN*16; i += 256) {
        int l = i >> 4, k = i & 15;
        Bsh[l*20 + k] = g_Bm[((size_t)s*LSEQ + l0 + l)*16 + k];
        Csh[l*20 + k] = g_Cm[((size_t)s*LSEQ + l0 + l)*16 + k];
    }
    const int fast = g_fast;
    float Areg[8];
    if (!fast) {
        #pragma unroll
        for (int k = 0; k < 8; k++) Areg[k] = -__expf(A_log[d*16 + kh*8 + k]);
    }
    float h[8];
    {
        const int ch = (s*128 + d)*16 + kh*8;
        #pragma unroll
        for (int k = 0; k < 8; k++) h[k] = g_Hc[c*NCHAN + ch + k];
    }
    const float Dd = Dp[d];
    __syncthreads();

    const float* pdt = g_dt   + ((size_t)s*LSEQ + l0)*128 + d;
    const float* pu  = g_ubuf + ((size_t)s*LSEQ + l0)*128 + d;
    const float* pz  = g_zbuf + ((size_t)s*LSEQ + l0)*128 + d;
    float*       py  = g_uraw + ((size_t)s*LSEQ + l0)*128 + d;

    if (fast) {
        #pragma unroll 2
        for (int l = 0; l < CLEN; l++) {
            float dt = pdt[l*128];
            float uu = pu[l*128];
            float zv = pz[l*128];
            float du = dt * uu;
            float p  = __expf(-dt);
            float q[8]; pow_tree8(p, q);
            float p8m = kh ? q[7] : 1.f;
            #pragma unroll
            for (int jj = 0; jj < 8; jj++) q[jj] *= p8m;
            float4 b0 = *(const float4*)&Bsh[l*20 + kh*8];
            float4 b1 = *(const float4*)&Bsh[l*20 + kh*8 + 4];
            float4 c0 = *(const float4*)&Csh[l*20 + kh*8];
            float4 c1 = *(const float4*)&Csh[l*20 + kh*8 + 4];
            float y = kh ? 0.f : Dd * uu;
            h[0] = q[0]*h[0] + du*b0.x;  y += h[0]*c0.x;
            h[1] = q[1]*h[1] + du*b0.y;  y += h[1]*c0.y;
            h[2] = q[2]*h[2] + du*b0.z;  y += h[2]*c0.z;
            h[3] = q[3]*h[3] + du*b0.w;  y += h[3]*c0.w;
            h[4] = q[4]*h[4] + du*b1.x;  y += h[4]*c1.x;
            h[5] = q[5]*h[5] + du*b1.y;  y += h[5]*c1.y;
            h[6] = q[6]*h[6] + du*b1.z;  y += h[6]*c1.z;
            h[7] = q[7]*h[7] + du*b1.w;  y += h[7]*c1.w;
            y += __shfl_xor_sync(0xffffffffu, y, 16);
            float sg = 1.f / (1.f + __expf(-zv));
            if (kh == 0) py[l*128] = y * zv * sg;
        }
    } else {
        #pragma unroll 2
        for (int l = 0; l < CLEN; l++) {
            float dt = pdt[l*128];
            float uu = pu[l*128];
            float zv = pz[l*128];
            float du = dt * uu;
            const float* pB = &Bsh[l*20 + kh*8];
            const float* pC = &Csh[l*20 + kh*8];
            float y = kh ? 0.f : Dd * uu;
            #pragma unroll
            for (int k = 0; k < 8; k++) {
                float a = __expf(dt * Areg[k]);
                h[k] = a*h[k] + du*pB[k];
                y   += h[k]*pC[k];
            }
            y += __shfl_xor_sync(0xffffffffu, y, 16);
            float sg = 1.f / (1.f + __expf(-zv));
            if (kh == 0) py[l*128] = y * zv * sg;
        }
    }
}

// ---------------- K4b: out_proj GEMM (f32x2) + skip -> g_xm ----------------
// grid (64, NSq), 256 threads, ~69KB smem
__global__ void __launch_bounds__(256)
k4b_outproj(const float* __restrict__ Wout, const float* __restrict__ skip) {
    extern __shared__ float sm[];
    float* ys  = sm;             // 128 x 66  y tile [d][l]
    float* wsh = ys + 128*66;    // 128 x 68  Wout^T [d][o]
    const int tid = threadIdx.x;
    const int s   = blockIdx.y;
    const int l0  = blockIdx.x * 64;

    for (int i = tid; i < 8192; i += 256) {       // y rows -> ys[d][l] (coalesced over d)
        int ll = i >> 7, dd = i & 127;
        ys[dd*66 + ll] = g_uraw[((size_t)s*LSEQ + l0 + ll)*128 + dd];
    }
    for (int i = tid; i < 8192; i += 256) {       // Wout -> wsh[d][o]
        int d = i & 127, o = i >> 7;
        wsh[d*68 + o] = Wout[i];
    }
    __syncthreads();

    const int to = tid >> 4;          // 16: o quad
    const int tl = tid & 15;          // 16: l quad
    const int o0 = to*4, lb = tl*4;
    u64 acc[4][2];
    #pragma unroll
    for (int i4 = 0; i4 < 4; i4++) { acc[i4][0] = 0ull; acc[i4][1] = 0ull; }

    #pragma unroll 2
    for (int d = 0; d < 128; d++) {
        float4 wq = *(const float4*)&wsh[d*68 + o0];
        const float* yp = ys + d*66 + lb;
        u64 xa = *(const u64*)yp;
        u64 xb = *(const u64*)(yp + 2);
        u64 w0 = packdup(wq.x), w1 = packdup(wq.y);
        u64 w2 = packdup(wq.z), w3 = packdup(wq.w);
        acc[0][0] = fma2(w0, xa, acc[0][0]); acc[0][1] = fma2(w0, xb, acc[0][1]);
        acc[1][0] = fma2(w1, xa, acc[1][0]); acc[1][1] = fma2(w1, xb, acc[1][1]);
        acc[2][0] = fma2(w2, xa, acc[2][0]); acc[2][1] = fma2(w2, xb, acc[2][1]);
        acc[3][0] = fma2(w3, xa, acc[3][0]); acc[3][1] = fma2(w3, xb, acc[3][1]);
    }

    float yv[4][4];
    #pragma unroll
    for (int i4 = 0; i4 < 4; i4++) {
        float2 a = unpk(acc[i4][0]), bb = unpk(acc[i4][1]);
        yv[i4][0] = a.x; yv[i4][1] = a.y; yv[i4][2] = bb.x; yv[i4][3] = bb.y;
    }

    const float sk = skip[0];
    const int p = s >> 1, b = s & 1;
    #pragma unroll
    for (int j = 0; j < 4; j++) {
        int l = l0 + lb + j;
        float4 pv = *(const float4*)&g_parts[((size_t)s*LSEQ + l)*64 + o0];
        float4 ov = make_float4(yv[0][j] + sk*pv.x, yv[1][j] + sk*pv.y,
                                yv[2][j] + sk*pv.z, yv[3][j] + sk*pv.w);
        *(float4*)&g_xm[((size_t)b*LSEQ + l)*256 + p*64 + o0] = ov;
    }
}

// ---------------- K5: final LN + 256x256 proj (f32x2) + bias + transpose ----------------
// grid (128, B, 2 o-halves), 256 threads, ~69KB smem
__global__ void __launch_bounds__(256)
k5_ln_proj(const float* __restrict__ lng, const float* __restrict__ lnb,
           const float* __restrict__ Wp, const float* __restrict__ bp,
           float* __restrict__ out) {
    extern __shared__ float sm[];
    float* xs  = sm;              // 256 x 34 (transposed [c][l])
    float* wt  = xs + 256*34;     // 64 x 132  Wp^T c-chunk [c'][o_local]
    float* gs  = wt + 64*132;     // 256
    float* bs  = gs + 256;        // 256
    float* mus = bs + 256;        // 32
    float* rss = mus + 32;        // 32

    const int tid = threadIdx.x;
    const int b   = blockIdx.y;
    const int z   = blockIdx.z;       // o-half
    const int l0  = blockIdx.x * 32;

    gs[tid] = lng[tid]; bs[tid] = lnb[tid];
    #pragma unroll 4
    for (int i = 0; i < 32; i++)      // g_xm[b][l][c] -> xs[c][l] (coalesced over c)
        xs[tid*34 + i] = g_xm[((size_t)b*LSEQ + l0 + i)*256 + tid];
    __syncthreads();

    const int w = tid >> 5, lane = tid & 31;
    for (int i = 0; i < 4; i++) {
        int ll = w*4 + i;
        float s = 0.f, s2 = 0.f;
        #pragma unroll
        for (int j = 0; j < 8; j++) {
            float v = xs[(lane + j*32)*34 + ll];
            s += v; s2 += v*v;
        }
        #pragma unroll
        for (int o = 16; o > 0; o >>= 1) {
            s  += __shfl_xor_sync(0xffffffffu, s,  o);
            s2 += __shfl_xor_sync(0xffffffffu, s2, o);
        }
        if (lane == 0) {
            float mu = s * (1.f/256.f);
            mus[ll] = mu;
            rss[ll] = rsqrtf(s2 * (1.f/256.f) - mu*mu + 1e-5f);
        }
    }
    __syncthreads();
    {
        const int c = tid;
        const float g = gs[c], bb = bs[c];
        #pragma unroll 4
        for (int ll = 0; ll < 32; ll++)
            xs[c*34 + ll] = (xs[c*34 + ll] - mus[ll]) * rss[ll] * g + bb;
    }

    const int to = tid >> 3;          // 32: o quad, ol0 = to*4 in [0,128)
    const int tl = tid & 7;           // 8: l quad
    const int ol0 = to*4, lb = tl*4;
    float4 pbv = *(const float4*)&bp[z*128 + ol0];
    u64 acc[4][2];
    acc[0][0] = packdup(pbv.x); acc[0][1] = acc[0][0];
    acc[1][0] = packdup(pbv.y); acc[1][1] = acc[1][0];
    acc[2][0] = packdup(pbv.z); acc[2][1] = acc[2][0];
    acc[3][0] = packdup(pbv.w); acc[3][1] = acc[3][0];

    for (int cchunk = 0; cchunk < 4; cchunk++) {
        const int c0 = cchunk*64;
        __syncthreads();
        #pragma unroll 4
        for (int i = 0; i < 32; i++) {         // Wp chunk -> wt[c'][o_local]
            int idx = i*256 + tid;
            int cc = idx & 63, ol = idx >> 6;
            wt[cc*132 + ol] = Wp[(z*128 + ol)*256 + c0 + cc];
        }
        __syncthreads();
        #pragma unroll 2
        for (int cc = 0; cc < 64; cc++) {
            float4 wq = *(const float4*)&wt[cc*132 + ol0];
            const float* xp = xs + (c0 + cc)*34 + lb;
            u64 xa = *(const u64*)xp;
            u64 xb = *(const u64*)(xp + 2);
            u64 w0 = packdup(wq.x), w1 = packdup(wq.y);
            u64 w2 = packdup(wq.z), w3 = packdup(wq.w);
            acc[0][0] = fma2(w0, xa, acc[0][0]); acc[0][1] = fma2(w0, xb, acc[0][1]);
            acc[1][0] = fma2(w1, xa, acc[1][0]); acc[1][1] = fma2(w1, xb, acc[1][1]);
            acc[2][0] = fma2(w2, xa, acc[2][0]); acc[2][1] = fma2(w2, xb, acc[2][1]);
            acc[3][0] = fma2(w3, xa, acc[3][0]); acc[3][1] = fma2(w3, xb, acc[3][1]);
        }
    }

    #pragma unroll
    for (int i4 = 0; i4 < 4; i4++) {
        float2 a = unpk(acc[i4][0]), bb = unpk(acc[i4][1]);
        *(float4*)&out[((size_t)b*256 + z*128 + ol0 + i4)*LSEQ + l0 + lb] =
            make_float4(a.x, a.y, bb.x, bb.y);
    }
}

// ---------------- launch ----------------
extern "C" void kernel_launch(void* const* d_in, const int* in_sizes, int n_in,
                              void* d_out, int out_size) {
    const float* x     = (const float*)d_in[0];
    const float* ln_g  = (const float*)d_in[1];
    const float* ln_b  = (const float*)d_in[2];
    const float* skip  = (const float*)d_in[3];
    const float* inw   = (const float*)d_in[4];
    const float* convw = (const float*)d_in[5];
    const float* convb = (const float*)d_in[6];
    const float* xprojw= (const float*)d_in[7];
    const float* dtw   = (const float*)d_in[8];
    const float* dtb   = (const float*)d_in[9];
    const float* A_log = (const float*)d_in[10];
    const float* Dp    = (const float*)d_in[11];
    const float* outw  = (const float*)d_in[12];
    const float* projw = (const float*)d_in[13];
    const float* projb = (const float*)d_in[14];
    float* out = (float*)d_out;

    const int SM1  = (256*34 + 64*132 + 256+256+32+32) * 4;
    const int SM2  = (35*130 + 32*130 + 36*130 + 32*40 + 128*5 + 128*5 + 128 + 128) * 4;
    const int SM4B = (128*66 + 128*68) * 4;
    const int SM5  = SM1;

    cudaFuncSetAttribute(k1_ln_inproj, cudaFuncAttributeMaxDynamicSharedMemorySize, SM1);
    cudaFuncSetAttribute(k2_conv,      cudaFuncAttributeMaxDynamicSharedMemorySize, SM2);
    cudaFuncSetAttribute(k4b_outproj,  cudaFuncAttributeMaxDynamicSharedMemorySize, SM4B);
    cudaFuncSetAttribute(k5_ln_proj,   cudaFuncAttributeMaxDynamicSharedMemorySize, SM5);

    k0_check<<<1, 256>>>(A_log);
    k1_ln_inproj<<<dim3(128, 2, 2), 256, SM1>>>(x, ln_g, ln_b, inw);
    k2_conv<<<dim3(128, NSq), 256, SM2>>>(convw, convb, xprojw, dtw, dtb);
    k3_scan1<<<dim3(NCHK, NSq), 256>>>(A_log);
    k3b_carry<<<NCHAN/256, 256>>>();
    k4_scan2<<<dim3(NCHK, NSq), 256>>>(A_log, Dp);
    k4b_outproj<<<dim3(64, NSq), 256, SM4B>>>(outw, skip);
    k5_ln_proj<<<dim3(128, 2, 2), 256, SM5>>>(ln_g, ln_b, projw, projb, out);
}

// round 16
// speedup vs baseline: 1.5143x; 1.0500x over previous
#include <cuda_runtime.h>
#include <math.h>

#define LSEQ 4096      // L = 16*16*16
#define NSq  8         // 4 parts * B=2 sequences
#define DI   128       // d_inner
#define DST  16        // d_state
#define NCHK 128       // scan chunks
#define CLEN 32        // chunk length
#define NCHAN (NSq*DI*DST)   // 16384 channels

typedef unsigned long long u64;

// ---------------- static device scratch (row layout [s][l][dim]) ----------------
__device__ __align__(16) float g_parts[NSq*LSEQ*64];   // [s][l][64]
__device__ __align__(16) float g_uraw [NSq*LSEQ*DI];   // pre-conv u (K1 -> K2, halo)
__device__ __align__(16) float g_zbuf [NSq*LSEQ*DI];
__device__ __align__(16) float g_ubuf [NSq*LSEQ*DI];
__device__ __align__(16) float g_dt   [NSq*LSEQ*DI];
__device__ __align__(16) float g_Bm   [NSq*LSEQ*DST];
__device__ __align__(16) float g_Cm   [NSq*LSEQ*DST];
__device__ float g_Ap[NCHK*NCHAN];
__device__ float g_Bp[NCHK*NCHAN];
__device__ float g_Hc[NCHK*NCHAN];
__device__ __align__(16) float g_xm[2*LSEQ*256];       // [b][l][256]
__device__ int g_fast;

// ---------------- f32x2 helpers ----------------
__device__ __forceinline__ u64 packdup(float w) {
    u64 r; unsigned int wi = __float_as_uint(w);
    asm("mov.b64 %0, {%1, %1};" : "=l"(r) : "r"(wi));
    return r;
}
__device__ __forceinline__ u64 fma2(u64 a, u64 b, u64 c) {
    u64 d; asm("fma.rn.f32x2 %0, %1, %2, %3;" : "=l"(d) : "l"(a), "l"(b), "l"(c));
    return d;
}
__device__ __forceinline__ float2 unpk(u64 v) {
    float2 f; asm("mov.b64 {%0, %1}, %2;" : "=f"(f.x), "=f"(f.y) : "l"(v));
    return f;
}

// ---------------- K0: detect A[d][k] == -(k+1) ----------------
__global__ void k0_check(const float* __restrict__ A_log) {
    __shared__ int ok;
    if (threadIdx.x == 0) ok = 1;
    __syncthreads();
    for (int i = threadIdx.x; i < DI*DST; i += blockDim.x) {
        int k = i & 15;
        float a = __expf(A_log[i]);
        if (fabsf(a - (float)(k + 1)) > 1e-3f * (float)(k + 1)) atomicAnd(&ok, 0);
    }
    __syncthreads();
    if (threadIdx.x == 0) g_fast = ok;
}

// ---------------- K1: LayerNorm + parts + in_proj (f32x2, full width) ----------------
// grid (128, B), 256 threads, ~69KB smem
__global__ void __launch_bounds__(256)
k1_ln_inproj(const float* __restrict__ x, const float* __restrict__ lng,
             const float* __restrict__ lnb, const float* __restrict__ W) {
    extern __shared__ float sm[];
    float* xs  = sm;              // 256 x 34  [c][l]
    float* ws  = xs + 256*34;     // 64 x 132  W^T e-chunk [d][e_local]  (offset 8704, 16B ok)
    float* gs  = ws + 64*132;     // 256
    float* bs  = gs + 256;        // 256
    float* mus = bs + 256;        // 32
    float* rss = mus + 32;        // 32

    const int tid = threadIdx.x;
    const int b   = blockIdx.y;
    const int l0  = blockIdx.x * 32;

    gs[tid] = lng[tid]; bs[tid] = lnb[tid];
    #pragma unroll 4
    for (int i = 0; i < 32; i++) {    // x -> xs[c][l]
        int idx = i*256 + tid;
        int cc = idx >> 5, ll = idx & 31;
        xs[cc*34 + ll] = x[(b*256 + cc)*LSEQ + l0 + ll];
    }
    __syncthreads();

    const int w = tid >> 5, lane = tid & 31;
    for (int i = 0; i < 4; i++) {     // LN stats
        int ll = w*4 + i;
        float s = 0.f, s2 = 0.f;
        #pragma unroll
        for (int j = 0; j < 8; j++) {
            float v = xs[(lane + j*32)*34 + ll];
            s += v; s2 += v*v;
        }
        #pragma unroll
        for (int o = 16; o > 0; o >>= 1) {
            s  += __shfl_xor_sync(0xffffffffu, s,  o);
            s2 += __shfl_xor_sync(0xffffffffu, s2, o);
        }
        if (lane == 0) {
            float mu = s * (1.f/256.f);
            mus[ll] = mu;
            rss[ll] = rsqrtf(s2 * (1.f/256.f) - mu*mu + 1e-5f);
        }
    }
    __syncthreads();

    {   // normalize + write all parts
        const int c = tid;
        const float g = gs[c], bb = bs[c];
        const int p = c >> 6, cq = c & 63;
        #pragma unroll 4
        for (int ll = 0; ll < 32; ll++) {
            float v = (xs[c*34 + ll] - mus[ll]) * rss[ll] * g + bb;
            xs[c*34 + ll] = v;
            g_parts[((p*2 + b)*LSEQ + l0 + ll)*64 + cq] = v;
        }
    }

    const int te = tid >> 3;          // 32: e quad
    const int tl = tid & 7;           // 8: l quad
    const int lb = tl*4;

    for (int ec = 0; ec < 2; ec++) {
        __syncthreads();
        #pragma unroll 4
        for (int i = 0; i < 32; i++) {    // W^T chunk -> ws[d][el]
            int idx = i*256 + tid;
            int d = idx & 63, el = idx >> 6;
            ws[d*132 + el] = W[(ec*128 + el)*64 + d];
        }
        __syncthreads();

        for (int p = 0; p < 4; p++) {
            const int s = p*2 + b;
            u64 acc[4][2];
            #pragma unroll
            for (int i4 = 0; i4 < 4; i4++) { acc[i4][0] = 0ull; acc[i4][1] = 0ull; }

            #pragma unroll 2
            for (int d = 0; d < 64; d++) {
                float4 wq = *(const float4*)&ws[d*132 + te*4];
                const float* xp = xs + (p*64 + d)*34 + lb;
                u64 xa = *(const u64*)xp;
                u64 xb = *(const u64*)(xp + 2);
                u64 w0 = packdup(wq.x), w1 = packdup(wq.y);
                u64 w2 = packdup(wq.z), w3 = packdup(wq.w);
                acc[0][0] = fma2(w0, xa, acc[0][0]); acc[0][1] = fma2(w0, xb, acc[0][1]);
                acc[1][0] = fma2(w1, xa, acc[1][0]); acc[1][1] = fma2(w1, xb, acc[1][1]);
                acc[2][0] = fma2(w2, xa, acc[2][0]); acc[2][1] = fma2(w2, xb, acc[2][1]);
                acc[3][0] = fma2(w3, xa, acc[3][0]); acc[3][1] = fma2(w3, xb, acc[3][1]);
            }

            float2 pa[4], pb2[4];
            #pragma unroll
            for (int i4 = 0; i4 < 4; i4++) { pa[i4] = unpk(acc[i4][0]); pb2[i4] = unpk(acc[i4][1]); }

            float* dst = (ec == 0) ? g_uraw : g_zbuf;
            float* base = dst + ((size_t)s*LSEQ + l0 + lb)*128 + te*4;
            *(float4*)(base      ) = make_float4(pa[0].x,  pa[1].x,  pa[2].x,  pa[3].x);
            *(float4*)(base + 128) = make_float4(pa[0].y,  pa[1].y,  pa[2].y,  pa[3].y);
            *(float4*)(base + 256) = make_float4(pb2[0].x, pb2[1].x, pb2[2].x, pb2[3].x);
            *(float4*)(base + 384) = make_float4(pb2[0].y, pb2[1].y, pb2[2].y, pb2[3].y);
        }
    }
}

// 8-power tree: q[j] = p^(j+1)
__device__ __forceinline__ void pow_tree8(float p, float* q) {
    float p2 = p*p, p4 = p2*p2;
    q[0]=p;     q[1]=p2;    q[2]=p2*p;    q[3]=p4;
    q[4]=p4*p;  q[5]=p4*p2; q[6]=p4*q[2]; q[7]=p4*p4;
}

// ---------------- K2: conv + silu + x_proj + dt_proj + softplus + SCAN PASS 1 ----------------
// grid (NCHK, NSq), 256 threads, ~63KB smem
// SMEM offsets chosen so dbc is 16B-aligned: ur padded to 4552 floats.
#define UR_SZ   4552               // 35*130 = 4550, +2 pad -> 16B-aligned successors
__global__ void __launch_bounds__(256)
k2_conv_scan1(const float* __restrict__ cw, const float* __restrict__ cb,
              const float* __restrict__ xw, const float* __restrict__ dtw,
              const float* __restrict__ dtb, const float* __restrict__ A_log) {
    extern __shared__ float sm[];
    float* ur   = sm;              // 35 x 130 (+2 pad); overlay dtt[128][33] after conv
    float* us   = ur + UR_SZ;      // 32 x 130  (offset 4552, *4 = 18208 B, 16B ok)
    float* xws  = us + 32*130;     // 36 x 130  (offset 8712, 16B ok)
    float* dbc  = xws + 36*130;    // 32 x 40   (offset 13392, *4 = 53568 B, 16B OK)
    float* cws  = dbc + 32*40;     // 128 x 5
    float* dtws = cws + 128*5;     // 128 x 5
    float* cbs  = dtws + 128*5;    // 128
    float* dtbs = cbs + 128;       // 128

    const int tid = threadIdx.x;
    const int s   = blockIdx.y;
    const int c   = blockIdx.x;
    const int l0  = c * CLEN;

    for (int i = tid; i < 128*4; i += 256) {
        int ch = i >> 2, j = i & 3;
        cws[ch*5 + j]  = cw[i];
        dtws[ch*5 + j] = dtw[i];
    }
    if (tid < 128) { cbs[tid] = cb[tid]; dtbs[tid] = dtb[tid]; }
    for (int i = tid; i < 36*128; i += 256) {
        int e = i >> 7, ch = i & 127;
        xws[e*130 + ch] = xw[i];
    }
    for (int i = tid; i < 35*128; i += 256) {
        int r = i >> 7, ch = i & 127;
        int l = l0 - 3 + r;
        ur[r*130 + ch] = (l >= 0) ? g_uraw[((size_t)s*LSEQ + l)*128 + ch] : 0.f;
    }
    __syncthreads();

    for (int i = tid; i < 32*128; i += 256) {     // conv + silu
        int ll = i >> 7, ch = i & 127;
        float a = cbs[ch];
        #pragma unroll
        for (int j = 0; j < 4; j++) a += cws[ch*5 + j] * ur[(ll + j)*130 + ch];
        float v = a / (1.f + __expf(-a));
        us[ll*130 + ch] = v;
        g_ubuf[((size_t)s*LSEQ + l0 + ll)*128 + ch] = v;
    }
    __syncthreads();

    for (int i = tid; i < 32*36; i += 256) {      // x_proj
        int ll = i / 36, e = i % 36;
        float a = 0.f;
        #pragma unroll 8
        for (int ch = 0; ch < 128; ch++) a += us[ll*130 + ch] * xws[e*130 + ch];
        dbc[ll*40 + e] = a;
    }
    __syncthreads();                               // ur dead; dbc ready

    float* dtt = ur;                               // overlay 128 x 33
    for (int i = tid; i < 32*16; i += 256) {       // write B, C rows
        int ll = i >> 4, k = i & 15;
        g_Bm[((size_t)s*LSEQ + l0 + ll)*16 + k] = dbc[ll*40 + 4 + k];
        g_Cm[((size_t)s*LSEQ + l0 + ll)*16 + k] = dbc[ll*40 + 20 + k];
    }
    for (int i = tid; i < 32*128; i += 256) {      // dt_proj + softplus
        int ll = i >> 7, d = i & 127;
        float a = dtbs[d];
        #pragma unroll
        for (int r = 0; r < 4; r++) a += dbc[ll*40 + r] * dtws[d*5 + r];
        float sp = (a > 20.f) ? a : log1pf(__expf(a));
        g_dt[((size_t)s*LSEQ + l0 + ll)*128 + d] = sp;
        dtt[d*33 + ll] = sp;
    }
    __syncthreads();

    // ---- fused scan pass 1: thread (d = tid&127, kh = tid>>7), data in SMEM ----
    const int d  = tid & 127;
    const int kh = tid >> 7;
    const int fast = g_fast;
    float Areg[8];
    if (!fast) {
        #pragma unroll
        for (int k = 0; k < 8; k++) Areg[k] = -__expf(A_log[d*16 + kh*8 + k]);
    }
    float h[8];
    #pragma unroll
    for (int k = 0; k < 8; k++) h[k] = 0.f;
    const int ch = (s*128 + d)*16 + kh*8;

    if (fast) {
        float P = 1.f;
        #pragma unroll 4
        for (int l = 0; l < CLEN; l++) {
            float dt = dtt[d*33 + l];
            float du = dt * us[l*130 + d];
            float p  = __expf(-dt);
            P *= p;
            float q[8]; pow_tree8(p, q);
            if (kh) {
                float p8 = q[7];
                #pragma unroll
                for (int jj = 0; jj < 8; jj++) q[jj] *= p8;
            }
            float4 b0 = *(const float4*)&dbc[l*40 + 4 + kh*8];
            float4 b1 = *(const float4*)&dbc[l*40 + 8 + kh*8];
            h[0] = q[0]*h[0] + du*b0.x;  h[1] = q[1]*h[1] + du*b0.y;
            h[2] = q[2]*h[2] + du*b0.z;  h[3] = q[3]*h[3] + du*b0.w;
            h[4] = q[4]*h[4] + du*b1.x;  h[5] = q[5]*h[5] + du*b1.y;
            h[6] = q[6]*h[6] + du*b1.z;  h[7] = q[7]*h[7] + du*b1.w;
        }
        float P2 = P*P, P4 = P2*P2, P8 = P4*P4;
        float Q = kh ? P8*P : P;
        #pragma unroll
        for (int k = 0; k < 8; k++) {
            g_Ap[c*NCHAN + ch + k] = Q;
            g_Bp[c*NCHAN + ch + k] = h[k];
            Q *= P;
        }
    } else {
        float ap[8];
        #pragma unroll
        for (int k = 0; k < 8; k++) ap[k] = 1.f;
        #pragma unroll 2
        for (int l = 0; l < CLEN; l++) {
            float dt = dtt[d*33 + l];
            float du = dt * us[l*130 + d];
            const float* pB = &dbc[l*40 + 4 + kh*8];
            #pragma unroll
            for (int k = 0; k < 8; k++) {
                float a = __expf(dt * Areg[k]);
                h[k]  = a*h[k] + du*pB[k];
                ap[k] *= a;
            }
        }
        #pragma unroll
        for (int k = 0; k < 8; k++) {
            g_Ap[c*NCHAN + ch + k] = ap[k];
            g_Bp[c*NCHAN + ch + k] = h[k];
        }
    }
}

// ---------------- K3b: inter-chunk carry scan ----------------
__global__ void __launch_bounds__(256)
k3b_carry() {
    int ch = blockIdx.x*256 + threadIdx.x;
    float h = 0.f;
    #pragma unroll 4
    for (int c = 0; c < NCHK; c++) {
        g_Hc[c*NCHAN + ch] = h;
        h = g_Ap[c*NCHAN + ch]*h + g_Bp[c*NCHAN + ch];
    }
}

// ---------------- K4: scan pass 2 + gate + out_proj + skip -> g_xm (fused) ----------------
// grid (NCHK, NSq), 256 threads, ~57KB smem (dynamic)
__global__ void __launch_bounds__(256)
k4_scan2_outproj(const float* __restrict__ A_log, const float* __restrict__ Dp,
                 const float* __restrict__ Wout, const float* __restrict__ skip) {
    extern __shared__ float sm[];
    float* Bsh = sm;              // 32 x 20
    float* Csh = Bsh + CLEN*20;   // 32 x 20  (offset 640, 16B ok)
    float* ys  = Csh + CLEN*20;   // 128 x 36 (offset 1280, 16B ok)
    float* wsh = ys + 128*36;     // 128 x 68 (offset 5888, 16B ok)

    const int tid  = threadIdx.x;
    const int w    = tid >> 5, lane = tid & 31;
    const int d    = w*16 + (lane & 15);
    const int kh   = lane >> 4;
    const int s    = blockIdx.y;
    const int c    = blockIdx.x;
    const int l0   = c * CLEN;

    for (int i = tid; i < CLEN*16; i += 256) {
        int l = i >> 4, k = i & 15;
        Bsh[l*20 + k] = g_Bm[((size_t)s*LSEQ + l0 + l)*16 + k];
        Csh[l*20 + k] = g_Cm[((size_t)s*LSEQ + l0 + l)*16 + k];
    }
    for (int i = tid; i < 8192; i += 256) {        // Wout -> wsh[d][o]
        int dd = i & 127, o = i >> 7;
        wsh[dd*68 + o] = Wout[o*128 + dd];
    }
    const int fast = g_fast;
    float Areg[8];
    if (!fast) {
        #pragma unroll
        for (int k = 0; k < 8; k++) Areg[k] = -__expf(A_log[d*16 + kh*8 + k]);
    }
    float h[8];
    {
        const int ch = (s*128 + d)*16 + kh*8;
        #pragma unroll
        for (int k = 0; k < 8; k++) h[k] = g_Hc[c*NCHAN + ch + k];
    }
    const float Dd = Dp[d];
    __syncthreads();

    const float* pdt = g_dt   + ((size_t)s*LSEQ + l0)*128 + d;
    const float* pu  = g_ubuf + ((size_t)s*LSEQ + l0)*128 + d;
    const float* pz  = g_zbuf + ((size_t)s*LSEQ + l0)*128 + d;

    if (fast) {
        #pragma unroll 2
        for (int l = 0; l < CLEN; l++) {
            float dt = pdt[l*128];
            float uu = pu[l*128];
            float zv = pz[l*128];
            float du = dt * uu;
            float p  = __expf(-dt);
            float q[8]; pow_tree8(p, q);
            float p8m = kh ? q[7] : 1.f;
            #pragma unroll
            for (int jj = 0; jj < 8; jj++) q[jj] *= p8m;
            float4 b0 = *(const float4*)&Bsh[l*20 + kh*8];
            float4 b1 = *(const float4*)&Bsh[l*20 + kh*8 + 4];
            float4 c0 = *(const float4*)&Csh[l*20 + kh*8];
            float4 c1 = *(const float4*)&Csh[l*20 + kh*8 + 4];
            float y = kh ? 0.f : Dd * uu;
            h[0] = q[0]*h[0] + du*b0.x;  y += h[0]*c0.x;
            h[1] = q[1]*h[1] + du*b0.y;  y += h[1]*c0.y;
            h[2] = q[2]*h[2] + du*b0.z;  y += h[2]*c0.z;
            h[3] = q[3]*h[3] + du*b0.w;  y += h[3]*c0.w;
            h[4] = q[4]*h[4] + du*b1.x;  y += h[4]*c1.x;
            h[5] = q[5]*h[5] + du*b1.y;  y += h[5]*c1.y;
            h[6] = q[6]*h[6] + du*b1.z;  y += h[6]*c1.z;
            h[7] = q[7]*h[7] + du*b1.w;  y += h[7]*c1.w;
            y += __shfl_xor_sync(0xffffffffu, y, 16);
            float sg = 1.f / (1.f + __expf(-zv));
            if (kh == 0) ys[d*36 + l] = y * zv * sg;
        }
    } else {
        #pragma unroll 2
        for (int l = 0; l < CLEN; l++) {
            float dt = pdt[l*128];
            float uu = pu[l*128];
            float zv = pz[l*128];
            float du = dt * uu;
            const float* pB = &Bsh[l*20 + kh*8];
            const float* pC = &Csh[l*20 + kh*8];
            float y = kh ? 0.f : Dd * uu;
            #pragma unroll
            for (int k = 0; k < 8; k++) {
                float a = __expf(dt * Areg[k]);
                h[k] = a*h[k] + du*pB[k];
                y   += h[k]*pC[k];
            }
            y += __shfl_xor_sync(0xffffffffu, y, 16);
            float sg = 1.f / (1.f + __expf(-zv));
            if (kh == 0) ys[d*36 + l] = y * zv * sg;
        }
    }
    __syncthreads();

    // out_proj: thread = (og 32 o-pairs, lg 8 l-quads)
    const int og = tid & 31, lg = tid >> 5;
    const int o0 = og*2, lb = lg*4;
    u64 acc[2][2];
    acc[0][0] = 0ull; acc[0][1] = 0ull; acc[1][0] = 0ull; acc[1][1] = 0ull;

    #pragma unroll 4
    for (int dd = 0; dd < 128; dd++) {
        float2 wv = *(const float2*)&wsh[dd*68 + o0];
        const float* yp = ys + dd*36 + lb;
        u64 ya = *(const u64*)yp;
        u64 yb = *(const u64*)(yp + 2);
        u64 w0 = packdup(wv.x), w1 = packdup(wv.y);
        acc[0][0] = fma2(w0, ya, acc[0][0]); acc[0][1] = fma2(w0, yb, acc[0][1]);
        acc[1][0] = fma2(w1, ya, acc[1][0]); acc[1][1] = fma2(w1, yb, acc[1][1]);
    }

    float a0[4], a1[4];
    {
        float2 t0 = unpk(acc[0][0]), t1 = unpk(acc[0][1]);
        a0[0]=t0.x; a0[1]=t0.y; a0[2]=t1.x; a0[3]=t1.y;
        float2 t2 = unpk(acc[1][0]), t3 = unpk(acc[1][1]);
        a1[0]=t2.x; a1[1]=t2.y; a1[2]=t3.x; a1[3]=t3.y;
    }

    const float sk = skip[0];
    const int p = s >> 1, b = s & 1;
    #pragma unroll
    for (int j = 0; j < 4; j++) {
        int l = l0 + lb + j;
        float2 pv = *(const float2*)&g_parts[((size_t)s*LSEQ + l)*64 + o0];
        float2 ov = make_float2(a0[j] + sk*pv.x, a1[j] + sk*pv.y);
        *(float2*)&g_xm[((size_t)b*LSEQ + l)*256 + p*64 + o0] = ov;
    }
}

// ---------------- K5: final LN + 256x256 proj (f32x2, full width) ----------------
// grid (128, B), 256 threads, ~69KB smem
__global__ void __launch_bounds__(256)
k5_ln_proj(const float* __restrict__ lng, const float* __restrict__ lnb,
           const float* __restrict__ Wp, const float* __restrict__ bp,
           float* __restrict__ out) {
    extern __shared__ float sm[];
    float* xs  = sm;              // 256 x 34 [c][l]
    float* wt  = xs + 256*34;     // 64 x 132  (offset 8704, 16B ok)
    float* gs  = wt + 64*132;     // 256
    float* bs  = gs + 256;        // 256
    float* mus = bs + 256;        // 32
    float* rss = mus + 32;        // 32

    const int tid = threadIdx.x;
    const int b   = blockIdx.y;
    const int l0  = blockIdx.x * 32;

    gs[tid] = lng[tid]; bs[tid] = lnb[tid];
    #pragma unroll 4
    for (int i = 0; i < 32; i++)
        xs[tid*34 + i] = g_xm[((size_t)b*LSEQ + l0 + i)*256 + tid];
    __syncthreads();

    const int w = tid >> 5, lane = tid & 31;
    for (int i = 0; i < 4; i++) {
        int ll = w*4 + i;
        float s = 0.f, s2 = 0.f;
        #pragma unroll
        for (int j = 0; j < 8; j++) {
            float v = xs[(lane + j*32)*34 + ll];
            s += v; s2 += v*v;
        }
        #pragma unroll
        for (int o = 16; o > 0; o >>= 1) {
            s  += __shfl_xor_sync(0xffffffffu, s,  o);
            s2 += __shfl_xor_sync(0xffffffffu, s2, o);
        }
        if (lane == 0) {
            float mu = s * (1.f/256.f);
            mus[ll] = mu;
            rss[ll] = rsqrtf(s2 * (1.f/256.f) - mu*mu + 1e-5f);
        }
    }
    __syncthreads();
    {
        const int c = tid;
        const float g = gs[c], bb = bs[c];
        #pragma unroll 4
        for (int ll = 0; ll < 32; ll++)
            xs[c*34 + ll] = (xs[c*34 + ll] - mus[ll]) * rss[ll] * g + bb;
    }

    const int to = tid >> 3;          // 32: o quad
    const int tl = tid & 7;           // 8: l quad
    const int ol0 = to*4, lb = tl*4;

    for (int z = 0; z < 2; z++) {
        float4 pbv = *(const float4*)&bp[z*128 + ol0];
        u64 acc[4][2];
        acc[0][0] = packdup(pbv.x); acc[0][1] = acc[0][0];
        acc[1][0] = packdup(pbv.y); acc[1][1] = acc[1][0];
        acc[2][0] = packdup(pbv.z); acc[2][1] = acc[2][0];
        acc[3][0] = packdup(pbv.w); acc[3][1] = acc[3][0];

        for (int cchunk = 0; cchunk < 4; cchunk++) {
            const int c0 = cchunk*64;
            __syncthreads();
            #pragma unroll 4
            for (int i = 0; i < 32; i++) {     // Wp chunk -> wt[c'][o_local]
                int idx = i*256 + tid;
                int cc = idx & 63, ol = idx >> 6;
                wt[cc*132 + ol] = Wp[(z*128 + ol)*256 + c0 + cc];
            }
            __syncthreads();
            #pragma unroll 2
            for (int cc = 0; cc < 64; cc++) {
                float4 wq = *(const float4*)&wt[cc*132 + ol0];
                const float* xp = xs + (c0 + cc)*34 + lb;
                u64 xa = *(const u64*)xp;
                u64 xb = *(const u64*)(xp + 2);
                u64 w0 = packdup(wq.x), w1 = packdup(wq.y);
                u64 w2 = packdup(wq.z), w3 = packdup(wq.w);
                acc[0][0] = fma2(w0, xa, acc[0][0]); acc[0][1] = fma2(w0, xb, acc[0][1]);
                acc[1][0] = fma2(w1, xa, acc[1][0]); acc[1][1] = fma2(w1, xb, acc[1][1]);
                acc[2][0] = fma2(w2, xa, acc[2][0]); acc[2][1] = fma2(w2, xb, acc[2][1]);
                acc[3][0] = fma2(w3, xa, acc[3][0]); acc[3][1] = fma2(w3, xb, acc[3][1]);
            }
        }

        #pragma unroll
        for (int i4 = 0; i4 < 4; i4++) {
            float2 a = unpk(acc[i4][0]), bb = unpk(acc[i4][1]);
            *(float4*)&out[((size_t)b*256 + z*128 + ol0 + i4)*LSEQ + l0 + lb] =
                make_float4(a.x, a.y, bb.x, bb.y);
        }
    }
}

// ---------------- launch ----------------
extern "C" void kernel_launch(void* const* d_in, const int* in_sizes, int n_in,
                              void* d_out, int out_size) {
    const float* x     = (const float*)d_in[0];
    const float* ln_g  = (const float*)d_in[1];
    const float* ln_b  = (const float*)d_in[2];
    const float* skip  = (const float*)d_in[3];
    const float* inw   = (const float*)d_in[4];
    const float* convw = (const float*)d_in[5];
    const float* convb = (const float*)d_in[6];
    const float* xprojw= (const float*)d_in[7];
    const float* dtw   = (const float*)d_in[8];
    const float* dtb   = (const float*)d_in[9];
    const float* A_log = (const float*)d_in[10];
    const float* Dp    = (const float*)d_in[11];
    const float* outw  = (const float*)d_in[12];
    const float* projw = (const float*)d_in[13];
    const float* projb = (const float*)d_in[14];
    float* out = (float*)d_out;

    const int SM1  = (256*34 + 64*132 + 256+256+32+32) * 4;
    const int SM2  = (4552 + 32*130 + 36*130 + 32*40 + 128*5 + 128*5 + 128 + 128) * 4;
    const int SM4  = (CLEN*20*2 + 128*36 + 128*68) * 4;
    const int SM5  = SM1;

    cudaFuncSetAttribute(k1_ln_inproj,     cudaFuncAttributeMaxDynamicSharedMemorySize, SM1);
    cudaFuncSetAttribute(k2_conv_scan1,    cudaFuncAttributeMaxDynamicSharedMemorySize, SM2);
    cudaFuncSetAttribute(k4_scan2_outproj, cudaFuncAttributeMaxDynamicSharedMemorySize, SM4);
    cudaFuncSetAttribute(k5_ln_proj,       cudaFuncAttributeMaxDynamicSharedMemorySize, SM5);

    k0_check<<<1, 256>>>(A_log);
    k1_ln_inproj<<<dim3(128, 2), 256, SM1>>>(x, ln_g, ln_b, inw);
    k2_conv_scan1<<<dim3(NCHK, NSq), 256, SM2>>>(convw, convb, xprojw, dtw, dtb, A_log);
    k3b_carry<<<NCHAN/256, 256>>>();
    k4_scan2_outproj<<<dim3(NCHK, NSq), 256, SM4>>>(A_log, Dp, outw, skip);
    k5_ln_proj<<<dim3(128, 2), 256, SM5>>>(ln_g, ln_b, projw, projb, out);
}